// round 3
// baseline (speedup 1.0000x reference)
#include <cuda_runtime.h>
#include <math.h>

#define BATCH 2
#define C 64
#define H 80
#define W 80
#define HW 6400

// ---- scratch layout (floats) ----
// conv outputs (offsets raw + sigmoid(mask)) per branch: [B][3*KK][H][W]
// transposed dcn weights per branch: [KK][C][64]
#define OFF3 0
#define OFF5 345600            // 2*27*6400
#define OFF7 1305600           // + 2*75*6400
#define WT3  3187200           // + 2*147*6400
#define WT5  3224064           // + 9*4096
#define WT7  3326464           // + 25*4096
#define SCRATCH_TOTAL 3527168  // + 49*4096

__device__ float g_scratch[SCRATCH_TOTAL];

// ============================================================
// Transpose w_dcn[oc][c][ky][kx] -> wt[tap][c][oc]
// ============================================================
__global__ void transpose_wdcn(const float* __restrict__ wsrc, int KK, int wtbase) {
    int i = blockIdx.x * 256 + threadIdx.x;
    if (i >= KK * 4096) return;
    int tap = i >> 12;
    int r = i & 4095;
    int c = r >> 6;
    int oc = r & 63;
    g_scratch[wtbase + i] = wsrc[(oc * 64 + c) * KK + tap];
}

// ============================================================
// Fused offset+mask conv. OC tile = 32 per block, 16x16 pixel tile.
// Each thread: 8 oc x 4 px accumulators (32 FMA / 12 LDS per step).
// ============================================================
template <int K>
__global__ __launch_bounds__(256) void conv_offmask(
    const float* __restrict__ x,
    const float* __restrict__ w_off, const float* __restrict__ b_off,
    const float* __restrict__ w_msk, const float* __restrict__ b_msk,
    int offbase, int nOCB)
{
    constexpr int KK  = K * K;
    constexpr int CH  = 3 * KK;
    constexpr int PAD = K / 2;
    constexpr int PH  = 16 + K - 1;   // patch height/width (even)
    constexpr int PWP = PH + 1;       // odd stride -> conflict-free
    constexpr int CC  = 4;

    __shared__ float xp[CC][PH][PWP];
    __shared__ float ws[CC][KK][33];

    const int tid = threadIdx.x;
    const int b   = blockIdx.z / nOCB;
    const int ocb = blockIdx.z % nOCB;
    const int ty  = blockIdx.y * 16;
    const int tx  = blockIdx.x * 16;

    const int ocg  = tid >> 6;            // 0..3 (8 oc each)
    const int pixg = tid & 63;
    const int py   = pixg & 15;           // row-in-tile
    const int px4  = (pixg >> 4) * 4;     // col base (0,4,8,12)

    float acc[8][4];
    #pragma unroll
    for (int j = 0; j < 8; j++)
        #pragma unroll
        for (int i = 0; i < 4; i++) acc[j][i] = 0.f;

    for (int c0 = 0; c0 < C; c0 += CC) {
        __syncthreads();
        // load x patch (zero-padded)
        for (int l = tid; l < CC * PH * PH; l += 256) {
            int cc = l / (PH * PH);
            int r  = l % (PH * PH);
            int ly = r / PH, lx = r % PH;
            int gy = ty - PAD + ly, gx = tx - PAD + lx;
            float v = 0.f;
            if (gy >= 0 && gy < H && gx >= 0 && gx < W)
                v = x[((b * C + c0 + cc) * H + gy) * W + gx];
            xp[cc][ly][lx] = v;
        }
        // load weights for the 32 oc of this block (zero beyond CH)
        for (int l = tid; l < 32 * CC * KK; l += 256) {
            int ocl = l / (CC * KK);
            int r   = l % (CC * KK);
            int cc  = r / KK, tap = r % KK;
            int oc  = ocb * 32 + ocl;
            float v = 0.f;
            if (oc < 2 * KK)      v = w_off[(oc * C + c0 + cc) * KK + tap];
            else if (oc < CH)     v = w_msk[((oc - 2 * KK) * C + c0 + cc) * KK + tap];
            ws[cc][tap][ocl] = v;
        }
        __syncthreads();

        #pragma unroll 1
        for (int cc = 0; cc < CC; cc++) {
            #pragma unroll 1
            for (int ky = 0; ky < K; ky++) {
                const float* xrow = &xp[cc][py + ky][px4];
                #pragma unroll
                for (int kx = 0; kx < K; kx++) {
                    float x0 = xrow[kx], x1 = xrow[kx + 1];
                    float x2 = xrow[kx + 2], x3 = xrow[kx + 3];
                    const float* wrow = &ws[cc][ky * K + kx][ocg * 8];
                    #pragma unroll
                    for (int j = 0; j < 8; j++) {
                        float wv = wrow[j];
                        acc[j][0] += wv * x0;
                        acc[j][1] += wv * x1;
                        acc[j][2] += wv * x2;
                        acc[j][3] += wv * x3;
                    }
                }
            }
        }
    }

    // epilogue: bias (+ sigmoid for mask channels), store to scratch
    #pragma unroll 1
    for (int j = 0; j < 8; j++) {
        int oc = ocb * 32 + ocg * 8 + j;
        if (oc >= CH) break;
        bool ismask = (oc >= 2 * KK);
        float bias = ismask ? b_msk[oc - 2 * KK] : b_off[oc];
        float* dst = &g_scratch[offbase + (b * CH + oc) * HW + (ty + py) * W + tx + px4];
        #pragma unroll
        for (int i = 0; i < 4; i++) {
            float v = acc[j][i] + bias;
            if (ismask) v = 1.f / (1.f + __expf(-v));
            dst[i] = v;
        }
    }
}

// ============================================================
// Deformable sample + DCN einsum.
// Block: 128 threads, 64 pixels, all 64 out channels.
// Per tap: corner precompute -> gather 64ch into smem -> 64x64x64 GEMM.
// Each thread: 8 oc x 4 px (float4) accumulators across all taps.
// ============================================================
template <int K>
__global__ __launch_bounds__(128) void deform_gemm(
    const float* __restrict__ x, int offbase, int wtbase,
    float* __restrict__ out, int obase)
{
    constexpr int KK  = K * K;
    constexpr int CH  = 3 * KK;
    constexpr int PAD = K / 2;

    __shared__ float samp[64][64];   // [c][pix]
    __shared__ float wtile[64][64];  // [c][oc]
    __shared__ float cw[64][4];      // corner weights (mask folded)
    __shared__ int   cidx[64][4];    // clamped gather indices

    const int tid = threadIdx.x;
    const int b   = blockIdx.y;
    const int p0  = blockIdx.x * 64;

    const int pixg = tid & 15;   // 4 px each
    const int ocg  = tid >> 4;   // 0..7, 8 oc each

    float4 acc[8];
    #pragma unroll
    for (int j = 0; j < 8; j++) acc[j] = make_float4(0.f, 0.f, 0.f, 0.f);

    const float* xb = x + b * C * HW;
    const float4* wtg = (const float4*)(g_scratch + wtbase);
    const float* ob = g_scratch + offbase + b * CH * HW;

    #pragma unroll 1
    for (int tap = 0; tap < KK; tap++) {
        __syncthreads();  // protect smem from previous iteration's readers

        // load this tap's weight slice [c][oc] (contiguous 16KB)
        {
            float4* w4 = (float4*)&wtile[0][0];
            const float4* src = wtg + tap * 1024;
            for (int l = tid; l < 1024; l += 128) w4[l] = src[l];
        }
        // per-pixel corner data
        if (tid < 64) {
            int p = p0 + tid;
            int h = p / W, w = p % W;
            float oy = ob[(2 * tap) * HW + p];
            float ox = ob[(2 * tap + 1) * HW + p];
            float m  = ob[(2 * KK + tap) * HW + p];
            float py = (float)(h - PAD + tap / K) + oy;
            float px = (float)(w - PAD + tap % K) + ox;
            float y0f = floorf(py), x0f = floorf(px);
            float fy = py - y0f, fx = px - x0f;
            int y0 = (int)y0f, x0 = (int)x0f;
            int y1 = y0 + 1, x1 = x0 + 1;
            bool vy0 = (y0 >= 0) && (y0 < H);
            bool vy1 = (y1 >= 0) && (y1 < H);
            bool vx0 = (x0 >= 0) && (x0 < W);
            bool vx1 = (x1 >= 0) && (x1 < W);
            int y0c = min(max(y0, 0), H - 1), y1c = min(max(y1, 0), H - 1);
            int x0c = min(max(x0, 0), W - 1), x1c = min(max(x1, 0), W - 1);
            cw[tid][0] = (vy0 && vx0) ? (1.f - fy) * (1.f - fx) * m : 0.f;
            cw[tid][1] = (vy0 && vx1) ? (1.f - fy) * fx * m : 0.f;
            cw[tid][2] = (vy1 && vx0) ? fy * (1.f - fx) * m : 0.f;
            cw[tid][3] = (vy1 && vx1) ? fy * fx * m : 0.f;
            cidx[tid][0] = y0c * W + x0c;
            cidx[tid][1] = y0c * W + x1c;
            cidx[tid][2] = y1c * W + x0c;
            cidx[tid][3] = y1c * W + x1c;
        }
        __syncthreads();

        // bilinear gather: each thread = 1 pixel, 32 channels
        {
            int pix = tid & 63;
            int ch0 = (tid >> 6) * 32;
            float w0 = cw[pix][0], w1 = cw[pix][1];
            float w2 = cw[pix][2], w3 = cw[pix][3];
            int i0 = cidx[pix][0], i1 = cidx[pix][1];
            int i2 = cidx[pix][2], i3 = cidx[pix][3];
            #pragma unroll 4
            for (int cc = 0; cc < 32; cc++) {
                const float* xc = xb + (ch0 + cc) * HW;
                samp[ch0 + cc][pix] = w0 * xc[i0] + w1 * xc[i1] + w2 * xc[i2] + w3 * xc[i3];
            }
        }
        __syncthreads();

        // GEMM accumulate: out[oc][pix] += wtile[c][oc] * samp[c][pix]
        {
            const float4* s4 = (const float4*)&samp[0][0];
            const float4* w4 = (const float4*)&wtile[0][0];
            #pragma unroll 4
            for (int c = 0; c < 64; c++) {
                float4 s  = s4[c * 16 + pixg];
                float4 wa = w4[c * 16 + ocg * 2];
                float4 wb = w4[c * 16 + ocg * 2 + 1];
                float ww[8];
                ww[0] = wa.x; ww[1] = wa.y; ww[2] = wa.z; ww[3] = wa.w;
                ww[4] = wb.x; ww[5] = wb.y; ww[6] = wb.z; ww[7] = wb.w;
                #pragma unroll
                for (int j = 0; j < 8; j++) {
                    acc[j].x += ww[j] * s.x;
                    acc[j].y += ww[j] * s.y;
                    acc[j].z += ww[j] * s.z;
                    acc[j].w += ww[j] * s.w;
                }
            }
        }
    }

    // write: out[b][obase+oc][p0 + pixg*4 .. +3]
    float4* o4 = (float4*)out;
    #pragma unroll
    for (int j = 0; j < 8; j++) {
        int oc = ocg * 8 + j;
        o4[((b * 192 + obase + oc) * HW + p0) / 4 + pixg] = acc[j];
    }
}

// ============================================================
extern "C" void kernel_launch(void* const* d_in, const int* in_sizes, int n_in,
                              void* d_out, int out_size) {
    (void)in_sizes; (void)n_in; (void)out_size;
    const float* x       = (const float*)d_in[0];
    const float* w_off3  = (const float*)d_in[1];
    const float* b_off3  = (const float*)d_in[2];
    const float* w_msk3  = (const float*)d_in[3];
    const float* b_msk3  = (const float*)d_in[4];
    const float* w_dcn3  = (const float*)d_in[5];
    const float* w_off5  = (const float*)d_in[6];
    const float* b_off5  = (const float*)d_in[7];
    const float* w_msk5  = (const float*)d_in[8];
    const float* b_msk5  = (const float*)d_in[9];
    const float* w_dcn5  = (const float*)d_in[10];
    const float* w_off7  = (const float*)d_in[11];
    const float* b_off7  = (const float*)d_in[12];
    const float* w_msk7  = (const float*)d_in[13];
    const float* b_msk7  = (const float*)d_in[14];
    const float* w_dcn7  = (const float*)d_in[15];
    float* out = (float*)d_out;

    transpose_wdcn<<<(9  * 4096 + 255) / 256, 256>>>(w_dcn3, 9,  WT3);
    transpose_wdcn<<<(25 * 4096 + 255) / 256, 256>>>(w_dcn5, 25, WT5);
    transpose_wdcn<<<(49 * 4096 + 255) / 256, 256>>>(w_dcn7, 49, WT7);

    conv_offmask<3><<<dim3(5, 5, BATCH * 1), 256>>>(x, w_off3, b_off3, w_msk3, b_msk3, OFF3, 1);
    conv_offmask<5><<<dim3(5, 5, BATCH * 3), 256>>>(x, w_off5, b_off5, w_msk5, b_msk5, OFF5, 3);
    conv_offmask<7><<<dim3(5, 5, BATCH * 5), 256>>>(x, w_off7, b_off7, w_msk7, b_msk7, OFF7, 5);

    deform_gemm<3><<<dim3(100, BATCH), 128>>>(x, OFF3, WT3, out, 0);
    deform_gemm<5><<<dim3(100, BATCH), 128>>>(x, OFF5, WT5, out, 64);
    deform_gemm<7><<<dim3(100, BATCH), 128>>>(x, OFF7, WT7, out, 128);
}

// round 6
// speedup vs baseline: 1.3109x; 1.3109x over previous
#include <cuda_runtime.h>
#include <math.h>

#define BATCH 2
#define C 64
#define H 80
#define W 80
#define HW 6400

// ---- scratch layout (floats) ----
#define OFF3 0
#define OFF5 345600            // 2*27*6400
#define OFF7 1305600           // + 2*75*6400
#define WT3  3187200           // + 2*147*6400
#define WT5  3224064           // + 9*4096
#define WT7  3326464           // + 25*4096
#define SCRATCH_TOTAL 3527168  // + 49*4096

__device__ float g_scratch[SCRATCH_TOTAL];

// ============================================================
// Merged transpose: w_dcn[oc][c][tap] -> wt[tap][c][oc], all 3 branches
// ============================================================
__global__ void transpose_all(const float* __restrict__ w3,
                              const float* __restrict__ w5,
                              const float* __restrict__ w7) {
    int i = blockIdx.x * 256 + threadIdx.x;
    if (i >= 83 * 4096) return;
    const float* src; int KK, base;
    if (i < 9 * 4096)       { src = w3; KK = 9;  base = WT3; }
    else if (i < 34 * 4096) { src = w5; KK = 25; base = WT5; i -= 9 * 4096; }
    else                    { src = w7; KK = 49; base = WT7; i -= 34 * 4096; }
    int tap = i >> 12;
    int r = i & 4095;
    int c = r >> 6;
    int oc = r & 63;
    g_scratch[base + i] = src[(oc * 64 + c) * KK + tap];
}

// ============================================================
// Conv body (templated on K), called from the merged conv kernel.
// 16x16 px tile, 32 oc / block. Weight smem rows strided to 40 floats so
// each thread's 8 weights are 2x LDS.128 (warp-uniform broadcast).
// x row segment held in registers across kx.
// ============================================================
#define CONV_SMEM_FLOATS 9864   // K=7: xp 4*22*23=2024 + ws 4*49*40=7840

template <int K>
__device__ __forceinline__ void conv_body(
    float* sm, const float* __restrict__ x,
    const float* __restrict__ w_off, const float* __restrict__ b_off,
    const float* __restrict__ w_msk, const float* __restrict__ b_msk,
    int offbase, int id, int nOCB)
{
    constexpr int KK  = K * K;
    constexpr int CH  = 3 * KK;
    constexpr int PAD = K / 2;
    constexpr int PH  = 16 + K - 1;
    constexpr int PWP = PH + 1;       // odd row stride
    constexpr int CC  = 4;
    constexpr int XPN = CC * PH * PWP;

    float* xp = sm;            // [CC][PH][PWP]
    float* ws = sm + XPN;      // [CC][KK][40]

    const int tid = threadIdx.x;
    const int bxx = id % 5;
    const int byy = (id / 5) % 5;
    const int z   = id / 25;
    const int b   = z / nOCB;
    const int ocb = z % nOCB;
    const int ty  = byy * 16;
    const int tx  = bxx * 16;

    const int ocg  = tid >> 6;          // uniform per warp
    const int pixg = tid & 63;
    const int py   = pixg & 15;
    const int px4  = (pixg >> 4) * 4;

    float acc[8][4];
    #pragma unroll
    for (int j = 0; j < 8; j++)
        #pragma unroll
        for (int i = 0; i < 4; i++) acc[j][i] = 0.f;

    for (int c0 = 0; c0 < C; c0 += CC) {
        __syncthreads();
        // x patch (zero-padded)
        for (int l = tid; l < CC * PH * PH; l += 256) {
            int cc = l / (PH * PH);
            int r  = l % (PH * PH);
            int ly = r / PH, lx = r % PH;
            int gy = ty - PAD + ly, gx = tx - PAD + lx;
            float v = 0.f;
            if (gy >= 0 && gy < H && gx >= 0 && gx < W)
                v = x[((b * C + c0 + cc) * H + gy) * W + gx];
            xp[(cc * PH + ly) * PWP + lx] = v;
        }
        // weights for this block's 32 oc, stride-40 rows
        for (int l = tid; l < 32 * CC * KK; l += 256) {
            int ocl = l / (CC * KK);
            int r   = l % (CC * KK);
            int cc  = r / KK, tap = r % KK;
            int oc  = ocb * 32 + ocl;
            float v = 0.f;
            if (oc < 2 * KK)  v = w_off[(oc * C + c0 + cc) * KK + tap];
            else if (oc < CH) v = w_msk[((oc - 2 * KK) * C + c0 + cc) * KK + tap];
            ws[(cc * KK + tap) * 40 + ocl] = v;
        }
        __syncthreads();

        #pragma unroll 1
        for (int cc = 0; cc < CC; cc++) {
            #pragma unroll 1
            for (int ky = 0; ky < K; ky++) {
                // hoist x row segment into registers
                float xr[K + 3];
                const float* xrow = &xp[(cc * PH + py + ky) * PWP + px4];
                #pragma unroll
                for (int i = 0; i < K + 3; i++) xr[i] = xrow[i];
                #pragma unroll
                for (int kx = 0; kx < K; kx++) {
                    const float4* wv =
                        (const float4*)&ws[(cc * KK + ky * K + kx) * 40 + ocg * 8];
                    float4 wa = wv[0];
                    float4 wb = wv[1];
                    float ww[8];
                    ww[0] = wa.x; ww[1] = wa.y; ww[2] = wa.z; ww[3] = wa.w;
                    ww[4] = wb.x; ww[5] = wb.y; ww[6] = wb.z; ww[7] = wb.w;
                    #pragma unroll
                    for (int j = 0; j < 8; j++) {
                        acc[j][0] += ww[j] * xr[kx + 0];
                        acc[j][1] += ww[j] * xr[kx + 1];
                        acc[j][2] += ww[j] * xr[kx + 2];
                        acc[j][3] += ww[j] * xr[kx + 3];
                    }
                }
            }
        }
    }

    // epilogue: bias (+ sigmoid for mask channels)
    #pragma unroll 1
    for (int j = 0; j < 8; j++) {
        int oc = ocb * 32 + ocg * 8 + j;
        if (oc >= CH) break;
        bool ismask = (oc >= 2 * KK);
        float bias = ismask ? b_msk[oc - 2 * KK] : b_off[oc];
        float* dst = &g_scratch[offbase + (b * CH + oc) * HW + (ty + py) * W + tx + px4];
        #pragma unroll
        for (int i = 0; i < 4; i++) {
            float v = acc[j][i] + bias;
            if (ismask) v = 1.f / (1.f + __expf(-v));
            dst[i] = v;
        }
    }
}

// Merged conv kernel: K=7 blocks first (longest work), then K=5, K=3.
__global__ __launch_bounds__(256) void conv_all(
    const float* __restrict__ x,
    const float* __restrict__ wo3, const float* __restrict__ bo3,
    const float* __restrict__ wm3, const float* __restrict__ bm3,
    const float* __restrict__ wo5, const float* __restrict__ bo5,
    const float* __restrict__ wm5, const float* __restrict__ bm5,
    const float* __restrict__ wo7, const float* __restrict__ bo7,
    const float* __restrict__ wm7, const float* __restrict__ bm7)
{
    __shared__ float sm[CONV_SMEM_FLOATS];
    int bx = blockIdx.x;
    if (bx < 250)      conv_body<7>(sm, x, wo7, bo7, wm7, bm7, OFF7, bx, 5);
    else if (bx < 400) conv_body<5>(sm, x, wo5, bo5, wm5, bm5, OFF5, bx - 250, 3);
    else               conv_body<3>(sm, x, wo3, bo3, wm3, bm3, OFF3, bx - 400, 1);
}

// ============================================================
// Deform body (templated on K). 64 px, 64 oc per block.
// ============================================================
template <int K>
__device__ __forceinline__ void deform_body(
    float* samp, float* wtile, float (*cw)[4], int (*cidx)[4],
    const float* __restrict__ x, int offbase, int wtbase,
    float* __restrict__ out, int obase, int b, int p0)
{
    constexpr int KK  = K * K;
    constexpr int CH  = 3 * KK;
    constexpr int PAD = K / 2;

    const int tid = threadIdx.x;
    const int pixg = tid & 15;   // 4 px each
    const int ocg  = tid >> 4;   // 8 oc each

    float4 acc[8];
    #pragma unroll
    for (int j = 0; j < 8; j++) acc[j] = make_float4(0.f, 0.f, 0.f, 0.f);

    const float* xb = x + b * C * HW;
    const float4* wtg = (const float4*)(g_scratch + wtbase);
    const float* ob = g_scratch + offbase + b * CH * HW;

    #pragma unroll 1
    for (int tap = 0; tap < KK; tap++) {
        __syncthreads();

        // weight slice [c][oc] for this tap (16KB contiguous)
        {
            float4* w4 = (float4*)wtile;
            const float4* src = wtg + tap * 1024;
            for (int l = tid; l < 1024; l += 128) w4[l] = src[l];
        }
        // per-pixel corner data
        if (tid < 64) {
            int p = p0 + tid;
            int h = p / W, w = p % W;
            float oy = ob[(2 * tap) * HW + p];
            float ox = ob[(2 * tap + 1) * HW + p];
            float m  = ob[(2 * KK + tap) * HW + p];
            float py = (float)(h - PAD + tap / K) + oy;
            float px = (float)(w - PAD + tap % K) + ox;
            float y0f = floorf(py), x0f = floorf(px);
            float fy = py - y0f, fx = px - x0f;
            int y0 = (int)y0f, x0 = (int)x0f;
            int y1 = y0 + 1, x1 = x0 + 1;
            bool vy0 = (y0 >= 0) && (y0 < H);
            bool vy1 = (y1 >= 0) && (y1 < H);
            bool vx0 = (x0 >= 0) && (x0 < W);
            bool vx1 = (x1 >= 0) && (x1 < W);
            int y0c = min(max(y0, 0), H - 1), y1c = min(max(y1, 0), H - 1);
            int x0c = min(max(x0, 0), W - 1), x1c = min(max(x1, 0), W - 1);
            cw[tid][0] = (vy0 && vx0) ? (1.f - fy) * (1.f - fx) * m : 0.f;
            cw[tid][1] = (vy0 && vx1) ? (1.f - fy) * fx * m : 0.f;
            cw[tid][2] = (vy1 && vx0) ? fy * (1.f - fx) * m : 0.f;
            cw[tid][3] = (vy1 && vx1) ? fy * fx * m : 0.f;
            cidx[tid][0] = y0c * W + x0c;
            cidx[tid][1] = y0c * W + x1c;
            cidx[tid][2] = y1c * W + x0c;
            cidx[tid][3] = y1c * W + x1c;
        }
        __syncthreads();

        // bilinear gather: 1 pixel per thread, 32 channels
        {
            int pix = tid & 63;
            int ch0 = (tid >> 6) * 32;
            float w0 = cw[pix][0], w1 = cw[pix][1];
            float w2 = cw[pix][2], w3 = cw[pix][3];
            int i0 = cidx[pix][0], i1 = cidx[pix][1];
            int i2 = cidx[pix][2], i3 = cidx[pix][3];
            #pragma unroll 4
            for (int cc = 0; cc < 32; cc++) {
                const float* xc = xb + (ch0 + cc) * HW;
                samp[(ch0 + cc) * 64 + pix] =
                    w0 * xc[i0] + w1 * xc[i1] + w2 * xc[i2] + w3 * xc[i3];
            }
        }
        __syncthreads();

        // GEMM accumulate: out[oc][pix] += wtile[c][oc] * samp[c][pix]
        {
            const float4* s4 = (const float4*)samp;
            const float4* w4 = (const float4*)wtile;
            #pragma unroll 4
            for (int c = 0; c < 64; c++) {
                float4 s  = s4[c * 16 + pixg];
                float4 wa = w4[c * 16 + ocg * 2];
                float4 wb = w4[c * 16 + ocg * 2 + 1];
                float ww[8];
                ww[0] = wa.x; ww[1] = wa.y; ww[2] = wa.z; ww[3] = wa.w;
                ww[4] = wb.x; ww[5] = wb.y; ww[6] = wb.z; ww[7] = wb.w;
                #pragma unroll
                for (int j = 0; j < 8; j++) {
                    acc[j].x += ww[j] * s.x;
                    acc[j].y += ww[j] * s.y;
                    acc[j].z += ww[j] * s.z;
                    acc[j].w += ww[j] * s.w;
                }
            }
        }
    }

    float4* o4 = (float4*)out;
    #pragma unroll
    for (int j = 0; j < 8; j++) {
        int oc = ocg * 8 + j;
        o4[((b * 192 + obase + oc) * HW + p0) / 4 + pixg] = acc[j];
    }
}

// Merged deform kernel: K=7 blocks first.
__global__ __launch_bounds__(128) void deform_all(
    const float* __restrict__ x, float* __restrict__ out)
{
    __shared__ float samp[64 * 64];
    __shared__ float wtile[64 * 64];
    __shared__ float cw[64][4];
    __shared__ int   cidx[64][4];

    int bx = blockIdx.x;
    int b  = blockIdx.y;
    if (bx < 100)
        deform_body<7>(samp, wtile, cw, cidx, x, OFF7, WT7, out, 128, b, bx * 64);
    else if (bx < 200)
        deform_body<5>(samp, wtile, cw, cidx, x, OFF5, WT5, out, 64, b, (bx - 100) * 64);
    else
        deform_body<3>(samp, wtile, cw, cidx, x, OFF3, WT3, out, 0, b, (bx - 200) * 64);
}

// ============================================================
extern "C" void kernel_launch(void* const* d_in, const int* in_sizes, int n_in,
                              void* d_out, int out_size) {
    (void)in_sizes; (void)n_in; (void)out_size;
    const float* x       = (const float*)d_in[0];
    const float* w_off3  = (const float*)d_in[1];
    const float* b_off3  = (const float*)d_in[2];
    const float* w_msk3  = (const float*)d_in[3];
    const float* b_msk3  = (const float*)d_in[4];
    const float* w_dcn3  = (const float*)d_in[5];
    const float* w_off5  = (const float*)d_in[6];
    const float* b_off5  = (const float*)d_in[7];
    const float* w_msk5  = (const float*)d_in[8];
    const float* b_msk5  = (const float*)d_in[9];
    const float* w_dcn5  = (const float*)d_in[10];
    const float* w_off7  = (const float*)d_in[11];
    const float* b_off7  = (const float*)d_in[12];
    const float* w_msk7  = (const float*)d_in[13];
    const float* b_msk7  = (const float*)d_in[14];
    const float* w_dcn7  = (const float*)d_in[15];
    float* out = (float*)d_out;

    transpose_all<<<(83 * 4096 + 255) / 256, 256>>>(w_dcn3, w_dcn5, w_dcn7);

    conv_all<<<450, 256>>>(x,
        w_off3, b_off3, w_msk3, b_msk3,
        w_off5, b_off5, w_msk5, b_msk5,
        w_off7, b_off7, w_msk7, b_msk7);

    deform_all<<<dim3(300, BATCH), 128>>>(x, out);
}